// round 7
// baseline (speedup 1.0000x reference)
#include <cuda_runtime.h>

// Weighted AUC via binned rank statistic — single fused kernel.
//   area = sum_{neg j} w_j * (pos weight above j);  AUC = area / (Wp * Wn)
// NBINS=2048, measured rel_err ~5e-7 (threshold 1e-3).
//
// Each CTA: smem histogram over its chunk -> TMA bulk add-reduce into g_red.
// The LAST CTA to finish per task (threadfence-reduction pattern) reduces the
// NG group copies, scans, writes out[task], and re-zeroes g_red + the counter
// so every graph replay starts from the same state.

#define N_TASKS 16
#define N_EX    2097152
#define NBINS   2048
#define LSHIFT  11                // label class offset shift: (int)label << 11
#define HBINS   (2 * NBINS)       // [neg | pos] halves = 4096 floats = 16 KB
#define NCHUNK  64                // hist CTAs per task
#define NG      4                 // accumulation groups (contention spreading)
#define HT      256               // threads per CTA
#define ELEMS_PER_CTA (N_EX / NCHUNK)          // 32768
#define VECS_PER_THR  (ELEMS_PER_CTA / 4 / HT) // 32
#define COLS4   (HBINS / 4)       // 1024 float4 columns
#define C4T     (COLS4 / HT)      // 4 float4 columns per thread in finalize

// Accumulated partials: [task][group][HBINS] (1 MB). Zero at module load;
// re-zeroed by the finalizer each run.
__device__ float g_red[(size_t)N_TASKS * NG * HBINS];
// Per-task arrival counters. Zero at module load; reset by the finalizer.
__device__ unsigned int g_count[N_TASKS];

__global__ void __launch_bounds__(HT, 8) auc_fused_kernel(
        const float* __restrict__ pred,
        const float* __restrict__ lab,
        const float* __restrict__ wt,
        float* __restrict__ out) {
    __shared__ float sh[HBINS];  // 16 KB histogram, reused in finalize
    __shared__ float s_wp[HT], s_wn[HT], s_num[HT];
    __shared__ float s_pref[HT + 1];
    __shared__ int   s_last;

    const int chunk = blockIdx.x;
    const int task  = blockIdx.y;
    const int tid   = threadIdx.x;

    float4* sh4 = reinterpret_cast<float4*>(sh);
    const float4 z = make_float4(0.f, 0.f, 0.f, 0.f);
#pragma unroll
    for (int i = tid; i < COLS4; i += HT) sh4[i] = z;
    __syncthreads();

    // ---------------- histogram phase ----------------
    {
        const size_t base = (size_t)task * N_EX + (size_t)chunk * ELEMS_PER_CTA;
        const float4* __restrict__ p4 = reinterpret_cast<const float4*>(pred + base);
        const float4* __restrict__ l4 = reinterpret_cast<const float4*>(lab  + base);
        const float4* __restrict__ w4 = reinterpret_cast<const float4*>(wt   + base);

#pragma unroll 2
        for (int it = 0; it < VECS_PER_THR; it++) {
            const int i = tid + it * HT;
            const float4 p = __ldcs(p4 + i);   // streaming, evict-first
            const float4 l = __ldcs(l4 + i);
            const float4 w = __ldcs(w4 + i);

            int b0 = (int)(p.x * (float)NBINS); b0 = b0 > NBINS - 1 ? NBINS - 1 : b0;
            int b1 = (int)(p.y * (float)NBINS); b1 = b1 > NBINS - 1 ? NBINS - 1 : b1;
            int b2 = (int)(p.z * (float)NBINS); b2 = b2 > NBINS - 1 ? NBINS - 1 : b2;
            int b3 = (int)(p.w * (float)NBINS); b3 = b3 > NBINS - 1 ? NBINS - 1 : b3;

            // labels are exact 0.0f / 1.0f
            atomicAdd(&sh[b0 + ((int)l.x << LSHIFT)], w.x);
            atomicAdd(&sh[b1 + ((int)l.y << LSHIFT)], w.y);
            atomicAdd(&sh[b2 + ((int)l.z << LSHIFT)], w.z);
            atomicAdd(&sh[b3 + ((int)l.w << LSHIFT)], w.w);
        }
    }
    __syncthreads();

    // ---------------- flush + arrival ----------------
    if (tid == 0) {
        const int grp = chunk & (NG - 1);
        float* dst = g_red + ((size_t)task * NG + grp) * HBINS;
        unsigned smem_u32 = (unsigned)__cvta_generic_to_shared(sh);
        asm volatile("fence.proxy.async.shared::cta;" ::: "memory");
        asm volatile(
            "cp.reduce.async.bulk.global.shared::cta.bulk_group.add.f32 "
            "[%0], [%1], %2;"
            :: "l"(dst), "r"(smem_u32), "r"((int)(HBINS * sizeof(float)))
            : "memory");
        asm volatile("cp.async.bulk.commit_group;" ::: "memory");
        // Full completion (not just .read): our reduce writes are performed
        // before we signal arrival.
        asm volatile("cp.async.bulk.wait_group 0;" ::: "memory");
        __threadfence();                                   // release
        const unsigned old = atomicAdd(&g_count[task], 1u);
        s_last = (old == NCHUNK - 1) ? 1 : 0;
    }
    __syncthreads();
    if (!s_last) return;

    // ---------------- finalize (last CTA of this task) ----------------
    __threadfence();   // acquire: all CTAs' reduce writes now visible

    // Reduce NG group copies into sh, re-zeroing as we go (same-thread order).
    {
        float4* __restrict__ src =
            reinterpret_cast<float4*>(g_red + (size_t)task * NG * HBINS);
#pragma unroll
        for (int c = 0; c < C4T; c++) {
            const int col = tid + c * HT;
            float4 s = z;
#pragma unroll
            for (int g = 0; g < NG; g++) {
                const float4 v = src[col + g * COLS4];
                s.x += v.x; s.y += v.y; s.z += v.z; s.w += v.w;
            }
#pragma unroll
            for (int g = 0; g < NG; g++) src[col + g * COLS4] = z;
            sh4[col] = s;
        }
    }
    __syncthreads();

    // Scan: descending prediction order, PB bins per thread.
    {
        const int PB = NBINS / HT;  // 8
        float swp = 0.0f, swn = 0.0f;
#pragma unroll
        for (int k = 0; k < PB; k++) {
            const int bin = NBINS - 1 - (tid * PB + k);
            swp += sh[NBINS + bin];
            swn += sh[bin];
        }
        s_wp[tid] = swp;
        s_wn[tid] = swn;
    }
    __syncthreads();

    if (tid == 0) {
        float acc = 0.0f;
        for (int i = 0; i < HT; i++) { s_pref[i] = acc; acc += s_wp[i]; }
        s_pref[HT] = acc;  // = W_pos
    }
    __syncthreads();

    {
        const int PB = NBINS / HT;
        float cum = s_pref[tid];  // positive weight strictly above these bins
        float num = 0.0f;
#pragma unroll
        for (int k = 0; k < PB; k++) {
            const int bin = NBINS - 1 - (tid * PB + k);
            const float wp = sh[NBINS + bin];
            const float wn = sh[bin];
            num += wn * (cum + 0.5f * wp);
            cum += wp;
        }
        s_num[tid] = num;
    }
    __syncthreads();

    if (tid == 0) {
        float tot = 0.0f, Wn = 0.0f;
        for (int i = 0; i < HT; i++) { tot += s_num[i]; Wn += s_wn[i]; }
        const float Wp = s_pref[HT];
        const double denom = (double)Wp * (double)Wn;
        out[task] = (denom == 0.0) ? 0.5f : (float)((double)tot / denom);
        g_count[task] = 0;   // reset for next graph replay
    }
}

extern "C" void kernel_launch(void* const* d_in, const int* in_sizes, int n_in,
                              void* d_out, int out_size) {
    // The three big float arrays in metadata order: predictions, labels, weights.
    const float* pred = nullptr;
    const float* lab  = nullptr;
    const float* wt   = nullptr;
    int found = 0;
    for (int i = 0; i < n_in; i++) {
        if (in_sizes[i] == N_TASKS * N_EX) {
            if      (found == 0) pred = (const float*)d_in[i];
            else if (found == 1) lab  = (const float*)d_in[i];
            else if (found == 2) wt   = (const float*)d_in[i];
            found++;
        }
    }

    dim3 grid(NCHUNK, N_TASKS);  // 1024 CTAs, 8/SM -> one full wave
    auc_fused_kernel<<<grid, HT>>>(pred, lab, wt, (float*)d_out);
}

// round 8
// speedup vs baseline: 1.0418x; 1.0418x over previous
#include <cuda_runtime.h>

// Weighted AUC via binned rank statistic.
//   area = sum_{neg j} w_j * (pos weight above j);  AUC = area / (Wp * Wn)
// NBINS=512: predicted rel_err ~1.2e-6 (measured 5.0e-7 @2048; threshold 1e-3).
//
// Pipeline (2 launches):
//   hist_kernel : 4 KB smem histogram per CTA, TMA bulk add-reduce into g_red.
//                 Small HBINS keeps the L2 reduce-ALU drain (~1M ops) at ~3 us.
//   auc_kernel  : reduce NG group copies + scan + finalize; re-zeroes g_red
//                 for the next graph replay (zeroed at module load initially).

#define N_TASKS 16
#define N_EX    2097152
#define NBINS   512
#define LSHIFT  9                 // label class offset shift: (int)label << 9
#define HBINS   (2 * NBINS)       // [neg | pos] halves = 1024 floats = 4 KB
#define NCHUNK  64                // hist CTAs per task
#define NG      4                 // accumulation groups (contention spreading)
#define HT      256               // hist kernel threads
#define AT      256               // auc kernel threads
#define ELEMS_PER_CTA (N_EX / NCHUNK)          // 32768
#define VECS_PER_THR  (ELEMS_PER_CTA / 4 / HT) // 32
#define COLS4   (HBINS / 4)       // 256 float4 columns

// Accumulated partials: [task][group][HBINS] (256 KB). Zero at module load;
// re-zeroed by auc_kernel each run.
__device__ float g_red[(size_t)N_TASKS * NG * HBINS];

__global__ void __launch_bounds__(HT, 8) hist_kernel(const float* __restrict__ pred,
                                                     const float* __restrict__ lab,
                                                     const float* __restrict__ wt) {
    __shared__ float sh[HBINS];  // 4 KB -> thread-limited 8 CTAs/SM, 64 warps

    const int chunk = blockIdx.x;
    const int task  = blockIdx.y;
    const int tid   = threadIdx.x;

    float4* sh4 = reinterpret_cast<float4*>(sh);
    if (tid < COLS4) sh4[tid] = make_float4(0.f, 0.f, 0.f, 0.f);
    __syncthreads();

    const size_t base = (size_t)task * N_EX + (size_t)chunk * ELEMS_PER_CTA;
    const float4* __restrict__ p4 = reinterpret_cast<const float4*>(pred + base);
    const float4* __restrict__ l4 = reinterpret_cast<const float4*>(lab  + base);
    const float4* __restrict__ w4 = reinterpret_cast<const float4*>(wt   + base);

#pragma unroll 2
    for (int it = 0; it < VECS_PER_THR; it++) {
        const int i = tid + it * HT;
        // Streaming loads (evict-first): read-once data.
        const float4 p = __ldcs(p4 + i);
        const float4 l = __ldcs(l4 + i);
        const float4 w = __ldcs(w4 + i);

        int b0 = (int)(p.x * (float)NBINS); b0 = b0 > NBINS - 1 ? NBINS - 1 : b0;
        int b1 = (int)(p.y * (float)NBINS); b1 = b1 > NBINS - 1 ? NBINS - 1 : b1;
        int b2 = (int)(p.z * (float)NBINS); b2 = b2 > NBINS - 1 ? NBINS - 1 : b2;
        int b3 = (int)(p.w * (float)NBINS); b3 = b3 > NBINS - 1 ? NBINS - 1 : b3;

        // labels are exact 0.0f / 1.0f
        atomicAdd(&sh[b0 + ((int)l.x << LSHIFT)], w.x);
        atomicAdd(&sh[b1 + ((int)l.y << LSHIFT)], w.y);
        atomicAdd(&sh[b2 + ((int)l.z << LSHIFT)], w.z);
        atomicAdd(&sh[b3 + ((int)l.w << LSHIFT)], w.w);
    }
    __syncthreads();

    // TMA bulk add-reduce: whole 4 KB smem histogram accumulated into this
    // task's group copy at L2. One instruction, no LSU store burst.
    if (tid == 0) {
        const int grp = chunk & (NG - 1);
        float* dst = g_red + ((size_t)task * NG + grp) * HBINS;
        unsigned smem_u32 = (unsigned)__cvta_generic_to_shared(sh);
        asm volatile("fence.proxy.async.shared::cta;" ::: "memory");
        asm volatile(
            "cp.reduce.async.bulk.global.shared::cta.bulk_group.add.f32 "
            "[%0], [%1], %2;"
            :: "l"(dst), "r"(smem_u32), "r"((int)(HBINS * sizeof(float)))
            : "memory");
        asm volatile("cp.async.bulk.commit_group;" ::: "memory");
        // smem must not be released before the TMA engine has read it.
        asm volatile("cp.async.bulk.wait_group.read 0;" ::: "memory");
    }
}

// Reduce NG group copies + scan + finalize; re-zero g_red for next replay.
// One CTA per task, 256 threads (one float4 column per thread).
__global__ void __launch_bounds__(AT) auc_kernel(float* __restrict__ out) {
    __shared__ float sh[HBINS];              // reduced: [neg | pos], 4 KB
    __shared__ float s_wp[AT], s_wn[AT], s_num[AT];
    __shared__ float s_pref[AT + 1];

    const int task = blockIdx.x;
    const int t    = threadIdx.x;

    // ---- reduce NG=4 group copies; re-zero in place (same-thread order) ----
    {
        float4* __restrict__ src =
            reinterpret_cast<float4*>(g_red + (size_t)task * NG * HBINS) + t;
        const float4 z = make_float4(0.f, 0.f, 0.f, 0.f);
        float4 s = z;
#pragma unroll
        for (int g = 0; g < NG; g++) {
            const float4 v = src[(size_t)g * COLS4];
            s.x += v.x; s.y += v.y; s.z += v.z; s.w += v.w;
        }
#pragma unroll
        for (int g = 0; g < NG; g++) src[(size_t)g * COLS4] = z;
        reinterpret_cast<float4*>(sh)[t] = s;
    }
    __syncthreads();

    // ---- scan: descending prediction order, PB=2 bins per thread ----
    {
        const int PB = NBINS / AT;  // 2
        float swp = 0.0f, swn = 0.0f;
#pragma unroll
        for (int k = 0; k < PB; k++) {
            const int bin = NBINS - 1 - (t * PB + k);
            swp += sh[NBINS + bin];
            swn += sh[bin];
        }
        s_wp[t] = swp;
        s_wn[t] = swn;
    }
    __syncthreads();

    if (t == 0) {
        float acc = 0.0f;
        for (int i = 0; i < AT; i++) { s_pref[i] = acc; acc += s_wp[i]; }
        s_pref[AT] = acc;  // = W_pos
    }
    __syncthreads();

    {
        const int PB = NBINS / AT;
        float cum = s_pref[t];   // positive weight strictly above these bins
        float num = 0.0f;
#pragma unroll
        for (int k = 0; k < PB; k++) {
            const int bin = NBINS - 1 - (t * PB + k);
            const float wp = sh[NBINS + bin];
            const float wn = sh[bin];
            num += wn * (cum + 0.5f * wp);
            cum += wp;
        }
        s_num[t] = num;
    }
    __syncthreads();

    if (t == 0) {
        float tot = 0.0f, Wn = 0.0f;
        for (int i = 0; i < AT; i++) { tot += s_num[i]; Wn += s_wn[i]; }
        const float Wp = s_pref[AT];
        const double denom = (double)Wp * (double)Wn;
        out[task] = (denom == 0.0) ? 0.5f : (float)((double)tot / denom);
    }
}

extern "C" void kernel_launch(void* const* d_in, const int* in_sizes, int n_in,
                              void* d_out, int out_size) {
    // The three big float arrays in metadata order: predictions, labels, weights.
    const float* pred = nullptr;
    const float* lab  = nullptr;
    const float* wt   = nullptr;
    int found = 0;
    for (int i = 0; i < n_in; i++) {
        if (in_sizes[i] == N_TASKS * N_EX) {
            if      (found == 0) pred = (const float*)d_in[i];
            else if (found == 1) lab  = (const float*)d_in[i];
            else if (found == 2) wt   = (const float*)d_in[i];
            found++;
        }
    }

    dim3 grid(NCHUNK, N_TASKS);  // 1024 CTAs, 8/SM -> one full wave
    hist_kernel<<<grid, HT>>>(pred, lab, wt);
    auc_kernel<<<N_TASKS, AT>>>((float*)d_out);
}

// round 9
// speedup vs baseline: 1.1369x; 1.0913x over previous
#include <cuda_runtime.h>

// Weighted AUC via binned rank statistic.
//   area = sum_{neg j} w_j * (pos weight above j);  AUC = area / (Wp * Wn)
// NBINS=2048 (best measured hist config), rel_err ~5e-7 (threshold 1e-3).
//
// Pipeline (2 launches):
//   hist_kernel : 16 KB smem histogram per CTA, TMA bulk add-reduce into g_red.
//   auc_kernel  : reduce NG copies + WARP-PARALLEL scan + finalize; re-zeroes
//                 g_red for the next replay (zeroed at module load initially).
//                 (Round-8 finding: the old serial t==0 scans cost ~9 us.)

#define N_TASKS 16
#define N_EX    2097152
#define NBINS   2048
#define LSHIFT  11                // label class offset shift: (int)label << 11
#define HBINS   (2 * NBINS)       // [neg | pos] halves = 4096 floats = 16 KB
#define NCHUNK  64                // hist CTAs per task
#define NG      4                 // accumulation groups (contention spreading)
#define HT      256               // hist kernel threads
#define AT      256               // auc kernel threads (8 warps)
#define NW      (AT / 32)         // 8 warps
#define ELEMS_PER_CTA (N_EX / NCHUNK)          // 32768
#define VECS_PER_THR  (ELEMS_PER_CTA / 4 / HT) // 32
#define COLS4   (HBINS / 4)       // 1024 float4 columns

// Accumulated partials: [task][group][HBINS] (1 MB). Zero at module load;
// re-zeroed by auc_kernel each run.
__device__ float g_red[(size_t)N_TASKS * NG * HBINS];

__global__ void __launch_bounds__(HT, 8) hist_kernel(const float* __restrict__ pred,
                                                     const float* __restrict__ lab,
                                                     const float* __restrict__ wt) {
    __shared__ float sh[HBINS];  // 16 KB -> 8 CTAs/SM, 64 warps

    const int chunk = blockIdx.x;
    const int task  = blockIdx.y;
    const int tid   = threadIdx.x;

    float4* sh4 = reinterpret_cast<float4*>(sh);
    const float4 z = make_float4(0.f, 0.f, 0.f, 0.f);
#pragma unroll
    for (int i = tid; i < COLS4; i += HT) sh4[i] = z;
    __syncthreads();

    const size_t base = (size_t)task * N_EX + (size_t)chunk * ELEMS_PER_CTA;
    const float4* __restrict__ p4 = reinterpret_cast<const float4*>(pred + base);
    const float4* __restrict__ l4 = reinterpret_cast<const float4*>(lab  + base);
    const float4* __restrict__ w4 = reinterpret_cast<const float4*>(wt   + base);

#pragma unroll 2
    for (int it = 0; it < VECS_PER_THR; it++) {
        const int i = tid + it * HT;
        // Streaming loads (evict-first): read-once data.
        const float4 p = __ldcs(p4 + i);
        const float4 l = __ldcs(l4 + i);
        const float4 w = __ldcs(w4 + i);

        int b0 = (int)(p.x * (float)NBINS); b0 = b0 > NBINS - 1 ? NBINS - 1 : b0;
        int b1 = (int)(p.y * (float)NBINS); b1 = b1 > NBINS - 1 ? NBINS - 1 : b1;
        int b2 = (int)(p.z * (float)NBINS); b2 = b2 > NBINS - 1 ? NBINS - 1 : b2;
        int b3 = (int)(p.w * (float)NBINS); b3 = b3 > NBINS - 1 ? NBINS - 1 : b3;

        // labels are exact 0.0f / 1.0f
        atomicAdd(&sh[b0 + ((int)l.x << LSHIFT)], w.x);
        atomicAdd(&sh[b1 + ((int)l.y << LSHIFT)], w.y);
        atomicAdd(&sh[b2 + ((int)l.z << LSHIFT)], w.z);
        atomicAdd(&sh[b3 + ((int)l.w << LSHIFT)], w.w);
    }
    __syncthreads();

    // TMA bulk add-reduce of the whole 16 KB histogram into this task's
    // group copy at L2.
    if (tid == 0) {
        const int grp = chunk & (NG - 1);
        float* dst = g_red + ((size_t)task * NG + grp) * HBINS;
        unsigned smem_u32 = (unsigned)__cvta_generic_to_shared(sh);
        asm volatile("fence.proxy.async.shared::cta;" ::: "memory");
        asm volatile(
            "cp.reduce.async.bulk.global.shared::cta.bulk_group.add.f32 "
            "[%0], [%1], %2;"
            :: "l"(dst), "r"(smem_u32), "r"((int)(HBINS * sizeof(float)))
            : "memory");
        asm volatile("cp.async.bulk.commit_group;" ::: "memory");
        asm volatile("cp.async.bulk.wait_group.read 0;" ::: "memory");
    }
}

// Reduce NG copies + parallel scan + finalize; re-zero g_red for next replay.
__global__ void __launch_bounds__(AT) auc_kernel(float* __restrict__ out) {
    __shared__ float sh[HBINS];              // reduced: [neg | pos], 16 KB
    __shared__ float s_warp[NW];             // warp totals / partials
    __shared__ float s_wn_warp[NW];
    __shared__ float s_num_warp[NW];
    __shared__ float s_wpos;

    const int task = blockIdx.x;
    const int t    = threadIdx.x;
    const int lane = t & 31;
    const int wid  = t >> 5;

    // ---- reduce NG=4 group copies; re-zero in place (same-thread order) ----
    {
        float4* __restrict__ src =
            reinterpret_cast<float4*>(g_red + (size_t)task * NG * HBINS);
        const float4 z = make_float4(0.f, 0.f, 0.f, 0.f);
#pragma unroll
        for (int c = 0; c < COLS4 / AT; c++) {       // 4 columns per thread
            const int col = t + c * AT;
            float4 s = z;
#pragma unroll
            for (int g = 0; g < NG; g++) {
                const float4 v = src[col + g * COLS4];
                s.x += v.x; s.y += v.y; s.z += v.z; s.w += v.w;
            }
#pragma unroll
            for (int g = 0; g < NG; g++) src[col + g * COLS4] = z;
            reinterpret_cast<float4*>(sh)[col] = s;
        }
    }
    __syncthreads();

    // ---- per-thread sums over PB=8 bins, descending prediction order ----
    const int PB = NBINS / AT;  // 8
    float swp = 0.0f, swn = 0.0f;
#pragma unroll
    for (int k = 0; k < PB; k++) {
        const int bin = NBINS - 1 - (t * PB + k);
        swp += sh[NBINS + bin];
        swn += sh[bin];
    }

    // ---- warp-parallel exclusive prefix of swp across all 256 threads ----
    float incl = swp;
#pragma unroll
    for (int d = 1; d < 32; d <<= 1) {
        const float v = __shfl_up_sync(0xffffffffu, incl, d);
        if (lane >= d) incl += v;
    }
    if (lane == 31) s_warp[wid] = incl;          // warp totals
    __syncthreads();
    if (wid == 0) {
        float wv = (lane < NW) ? s_warp[lane] : 0.0f;
        float wincl = wv;
#pragma unroll
        for (int d = 1; d < NW; d <<= 1) {
            const float v = __shfl_up_sync(0xffffffffu, wincl, d);
            if (lane >= d) wincl += v;
        }
        if (lane < NW) s_warp[lane] = wincl - wv;    // exclusive warp offsets
        if (lane == NW - 1) s_wpos = wincl;          // total W_pos
    }
    __syncthreads();
    const float pref = s_warp[wid] + (incl - swp);   // exclusive prefix for t

    // ---- numerator for this thread's bins ----
    float cum = pref;    // positive weight strictly above these bins
    float num = 0.0f;
#pragma unroll
    for (int k = 0; k < PB; k++) {
        const int bin = NBINS - 1 - (t * PB + k);
        const float wp = sh[NBINS + bin];
        const float wn = sh[bin];
        num += wn * (cum + 0.5f * wp);
        cum += wp;
    }

    // ---- tree-reduce num and swn ----
#pragma unroll
    for (int d = 16; d >= 1; d >>= 1) {
        num += __shfl_down_sync(0xffffffffu, num, d);
        swn += __shfl_down_sync(0xffffffffu, swn, d);
    }
    if (lane == 0) { s_num_warp[wid] = num; s_wn_warp[wid] = swn; }
    __syncthreads();

    if (t == 0) {
        float tot = 0.0f, Wn = 0.0f;
#pragma unroll
        for (int i = 0; i < NW; i++) { tot += s_num_warp[i]; Wn += s_wn_warp[i]; }
        const float Wp = s_wpos;
        const double denom = (double)Wp * (double)Wn;
        out[task] = (denom == 0.0) ? 0.5f : (float)((double)tot / denom);
    }
}

extern "C" void kernel_launch(void* const* d_in, const int* in_sizes, int n_in,
                              void* d_out, int out_size) {
    // The three big float arrays in metadata order: predictions, labels, weights.
    const float* pred = nullptr;
    const float* lab  = nullptr;
    const float* wt   = nullptr;
    int found = 0;
    for (int i = 0; i < n_in; i++) {
        if (in_sizes[i] == N_TASKS * N_EX) {
            if      (found == 0) pred = (const float*)d_in[i];
            else if (found == 1) lab  = (const float*)d_in[i];
            else if (found == 2) wt   = (const float*)d_in[i];
            found++;
        }
    }

    dim3 grid(NCHUNK, N_TASKS);  // 1024 CTAs, 8/SM -> one full wave
    hist_kernel<<<grid, HT>>>(pred, lab, wt);
    auc_kernel<<<N_TASKS, AT>>>((float*)d_out);
}